// round 4
// baseline (speedup 1.0000x reference)
#include <cuda_runtime.h>

#define WARPS_PER_BLOCK 8
#define THREADS 256
#define MAX_BLOCKS 4096

__device__ __align__(16) float g_w2[64];
__device__ float g_partials[MAX_BLOCKS * 3];
__device__ unsigned int g_count = 0;

__device__ __forceinline__ float wsum(float v) {
#pragma unroll
    for (int o = 16; o > 0; o >>= 1) v += __shfl_xor_sync(0xffffffffu, v, o);
    return v;
}

// -log(sigmoid(x)) = softplus(-x); fast + stable (tol is 1e-3)
__device__ __forceinline__ float nlsig(float x) {
    float z = -x;
    return fmaxf(z, 0.f) + __logf(1.f + __expf(-fabsf(z)));
}

// w2[d] = sum_e att_w_W[d,e] * att_v_W[64+e]
__global__ void precompute_w2(const float* __restrict__ W, const float* __restrict__ vW) {
    const int d = threadIdx.x;
    const float4* Wr = (const float4*)(W + d * 64);
    const float4* vr = (const float4*)(vW + 64);
    float s = 0.f;
#pragma unroll
    for (int e = 0; e < 16; e++) {
        float4 w = __ldg(Wr + e);
        float4 v = __ldg(vr + e);
        s += w.x * v.x + w.y * v.y + w.z * v.z + w.w * v.w;
    }
    g_w2[d] = s;
}

__global__ void __launch_bounds__(THREADS, 5) actr_main(
    const int* __restrict__ u_id, const int* __restrict__ anchor_i_id,
    const int* __restrict__ pos_r_id, const int* __restrict__ pos_i_id,
    const int* __restrict__ neg_r_id, const int* __restrict__ neg_i_id,
    const int* __restrict__ neg_ri_id, const int* __restrict__ item_meta,
    const float* __restrict__ user_emb, const float* __restrict__ rel_emb,
    const float* __restrict__ item_emb, const float* __restrict__ item_emb_r,
    const float* __restrict__ item_bias, const float* __restrict__ rel_bias,
    const float* __restrict__ meta_emb,
    float* __restrict__ out, int B, float invB)
{
    const int lane = threadIdx.x & 31;
    const int wid = threadIdx.x >> 5;
    const int b = blockIdx.x * WARPS_PER_BLOCK + wid;

    float seqL = 0.f, relL = 0.f, itmL = 0.f;

    if (b < B) {
        // ---- indices first: start the two-level dependent chain ASAP
        const int aid  = __ldg(anchor_i_id + b);
        const int pid  = __ldg(pos_i_id + b);
        const int nid  = __ldg(neg_i_id + b);
        const int uid  = __ldg(u_id + b);
        const int nrid = __ldg(neg_ri_id + b);
        const int prid = __ldg(pos_r_id + b);
        const int nrel = __ldg(neg_r_id + b);

        // item_meta rows: one int4 gather each (dependent meta_emb gathers follow)
        int4 ma = __ldg((const int4*)item_meta + aid);
        int4 mp = __ldg((const int4*)item_meta + pid);
        int4 mn = __ldg((const int4*)item_meta + nid);
        int mai[4] = {ma.x, ma.y, ma.z, ma.w};
        int mpi[4] = {mp.x, mp.y, mp.z, mp.w};
        int mni[4] = {mn.x, mn.y, mn.z, mn.w};

        // big-table gathers: streaming (evict-first) so meta_emb stays L2-resident
        float2 u   = __ldcs((const float2*)user_emb   + (size_t)uid  * 32 + lane);
        float2 ar  = __ldcs((const float2*)item_emb_r + (size_t)aid  * 32 + lane);
        float2 a   = __ldcs((const float2*)item_emb   + (size_t)aid  * 32 + lane);
        float2 p   = __ldcs((const float2*)item_emb   + (size_t)pid  * 32 + lane);
        float2 n   = __ldcs((const float2*)item_emb   + (size_t)nid  * 32 + lane);
        float2 nri = __ldcs((const float2*)item_emb   + (size_t)nrid * 32 + lane);
        float2 w2  = __ldg((const float2*)g_w2 + lane);

        float2 re[3];
#pragma unroll
        for (int r = 0; r < 3; r++)
            re[r] = __ldg((const float2*)rel_emb + r * 32 + lane);

        float2 am[4], pm[4], nm[4];
#pragma unroll
        for (int g = 0; g < 4; g++) {
            am[g] = __ldg((const float2*)meta_emb + (size_t)mai[g] * 32 + lane);
            pm[g] = __ldg((const float2*)meta_emb + (size_t)mpi[g] * 32 + lane);
            nm[g] = __ldg((const float2*)meta_emb + (size_t)mni[g] * 32 + lane);
        }

        // ---- relation prediction: softmax_r( rel_bias[r] - ||u + a_r - rel_emb[r]||^2 )
        float rw[3];
#pragma unroll
        for (int r = 0; r < 3; r++) {
            float dx = u.x + ar.x - re[r].x;
            float dy = u.y + ar.y - re[r].y;
            rw[r] = __ldg(rel_bias + r) - wsum(dx * dx + dy * dy);
        }
        float mx = fmaxf(rw[0], fmaxf(rw[1], rw[2]));
        float ssum = 0.f;
#pragma unroll
        for (int r = 0; r < 3; r++) { rw[r] = __expf(rw[r] - mx); ssum += rw[r]; }
        float inv = __frcp_rn(ssum);
#pragma unroll
        for (int r = 0; r < 3; r++) rw[r] *= inv;

        // ---- attention coef: softmax_c( i_plus[c] . w2 )  (wu & biases cancel in softmax)
        float cf[5];
        cf[0] = wsum(a.x * w2.x + a.y * w2.y);
#pragma unroll
        for (int g = 0; g < 4; g++)
            cf[1 + g] = wsum(am[g].x * w2.x + am[g].y * w2.y);
        mx = cf[0];
#pragma unroll
        for (int c = 1; c < 5; c++) mx = fmaxf(mx, cf[c]);
        ssum = 0.f;
#pragma unroll
        for (int c = 0; c < 5; c++) { cf[c] = __expf(cf[c] - mx); ssum += cf[c]; }
        inv = __frcp_rn(ssum);
#pragma unroll
        for (int c = 0; c < 5; c++) cf[c] *= inv;

        // ---- rbar = sum_r rel[r]*rue[r]  (srp term cancels in pos-neg difference)
        const float GAMMA = 0.5f;
        float2 rbar;
        rbar.x = GAMMA * (rw[0] * re[0].x + rw[1] * re[1].x + rw[2] * re[2].x) + (1.f - GAMMA) * u.x;
        rbar.y = GAMMA * (rw[0] * re[0].y + rw[1] * re[1].y + rw[2] * re[2].y) + (1.f - GAMMA) * u.y;

        // ---- seq score difference in ONE reduction:
        //   posR-negR = (biasP-biasN) - wsum( (sp_partial - sn_partial) )
        float diffpn;
        {
            float sdp = 0.f, dbxp = 0.f, dbyp = 0.f;
            float sdn = 0.f, dbxn = 0.f, dbyn = 0.f;
            float dx = a.x - p.x, dy = a.y - p.y;
            sdp += cf[0] * (dx * dx + dy * dy); dbxp += cf[0] * dx; dbyp += cf[0] * dy;
            dx = a.x - n.x; dy = a.y - n.y;
            sdn += cf[0] * (dx * dx + dy * dy); dbxn += cf[0] * dx; dbyn += cf[0] * dy;
#pragma unroll
            for (int g = 0; g < 4; g++) {
                dx = am[g].x - pm[g].x; dy = am[g].y - pm[g].y;
                sdp += cf[1 + g] * (dx * dx + dy * dy);
                dbxp += cf[1 + g] * dx; dbyp += cf[1 + g] * dy;
                dx = am[g].x - nm[g].x; dy = am[g].y - nm[g].y;
                sdn += cf[1 + g] * (dx * dx + dy * dy);
                dbxn += cf[1 + g] * dx; dbyn += cf[1 + g] * dy;
            }
            float sp = sdp + 2.f * (dbxp * rbar.x + dbyp * rbar.y);
            float sn = sdn + 2.f * (dbxn * rbar.x + dbyn * rbar.y);
            diffpn = wsum(sp - sn);
        }
        float biasP = __ldg(item_bias + pid);
        float biasN = __ldg(item_bias + nid);
        seqL = nlsig((biasP - biasN) - diffpn);

        // ---- relation loss
        float prs = (prid == 0) ? rw[0] : ((prid == 1) ? rw[1] : rw[2]);
        float nrs = (nrel == 0) ? rw[0] : ((nrel == 1) ? rw[1] : rw[2]);
        relL = nlsig(prs - nrs);

        // ---- item loss in ONE reduction
        float2 iir;
        iir.x = (prid == 0) ? re[0].x : ((prid == 1) ? re[1].x : re[2].x);
        iir.y = (prid == 0) ? re[0].y : ((prid == 1) ? re[1].y : re[2].y);
        float px = a.x + iir.x - p.x,   py = a.y + iir.y - p.y;
        float qx = a.x + iir.x - nri.x, qy = a.y + iir.y - nri.y;
        float di = wsum((px * px + py * py) - (qx * qx + qy * qy));
        float biasNR = __ldg(item_bias + nrid);
        itmL = nlsig((biasP - biasNR) - di);
    }

    // ---- deterministic block-level partial sum
    __shared__ float sh[WARPS_PER_BLOCK][3];
    __shared__ bool is_last;
    if (lane == 0) { sh[wid][0] = seqL; sh[wid][1] = relL; sh[wid][2] = itmL; }
    __syncthreads();
    if (threadIdx.x == 0) {
        float s0 = 0.f, s1 = 0.f, s2 = 0.f;
#pragma unroll
        for (int w = 0; w < WARPS_PER_BLOCK; w++) {
            s0 += sh[w][0]; s1 += sh[w][1]; s2 += sh[w][2];
        }
        g_partials[blockIdx.x * 3 + 0] = s0;
        g_partials[blockIdx.x * 3 + 1] = s1;
        g_partials[blockIdx.x * 3 + 2] = s2;
        __threadfence();
        unsigned int old = atomicAdd(&g_count, 1u);
        is_last = (old == gridDim.x - 1);
    }
    __syncthreads();

    // ---- last arriving block does the final (fixed-order, deterministic) reduce
    if (is_last) {
        const int nblocks = gridDim.x;
        __shared__ float shf[3];
        if (wid < 3) {
            float s = 0.f;
            for (int i = lane; i < nblocks; i += 32) s += g_partials[i * 3 + wid];
            s = wsum(s) * invB;
            if (lane == 0) shf[wid] = s;
        }
        __syncthreads();
        if (threadIdx.x == 0) {
            float seq = shf[0], rel = shf[1], itm = shf[2];
            out[0] = seq + rel + itm;   // loss (ALPHA=BETA=1)
            out[1] = rel;               // relation_loss
            out[2] = seq;               // seq_loss
            out[3] = itm;               // item_loss
            g_count = 0;                // reset for next graph replay
        }
    }
}

extern "C" void kernel_launch(void* const* d_in, const int* in_sizes, int n_in,
                              void* d_out, int out_size) {
    const int*   u_id       = (const int*)d_in[0];
    const int*   anchor_i   = (const int*)d_in[1];
    const int*   pos_r      = (const int*)d_in[2];
    const int*   pos_i      = (const int*)d_in[3];
    const int*   neg_r      = (const int*)d_in[4];
    const int*   neg_i      = (const int*)d_in[5];
    const int*   neg_ri     = (const int*)d_in[6];
    const int*   item_meta  = (const int*)d_in[7];
    const float* user_emb   = (const float*)d_in[8];
    const float* rel_emb    = (const float*)d_in[9];
    const float* item_emb   = (const float*)d_in[10];
    const float* item_emb_r = (const float*)d_in[11];
    const float* item_bias  = (const float*)d_in[12];
    const float* rel_bias   = (const float*)d_in[13];
    const float* meta_emb   = (const float*)d_in[14];
    const float* att_w_W    = (const float*)d_in[15];
    const float* att_v_W    = (const float*)d_in[17];

    const int B = in_sizes[0];
    int nblocks = (B + WARPS_PER_BLOCK - 1) / WARPS_PER_BLOCK;
    if (nblocks > MAX_BLOCKS) nblocks = MAX_BLOCKS;  // B=16384 -> 2048

    precompute_w2<<<1, 64>>>(att_w_W, att_v_W);
    actr_main<<<nblocks, THREADS>>>(u_id, anchor_i, pos_r, pos_i, neg_r, neg_i, neg_ri,
                                    item_meta, user_emb, rel_emb, item_emb, item_emb_r,
                                    item_bias, rel_bias, meta_emb,
                                    (float*)d_out, B, 1.0f / (float)B);
}

// round 5
// speedup vs baseline: 1.2142x; 1.2142x over previous
#include <cuda_runtime.h>

#define WARPS_PER_BLOCK 8
#define THREADS 256
#define GRID_BLOCKS 592
#define MAX_BLOCKS 1024

__device__ __align__(16) float g_w2[64];
__device__ float g_partials[MAX_BLOCKS * 3];
__device__ unsigned int g_count = 0;

__device__ __forceinline__ float wsum(float v) {
#pragma unroll
    for (int o = 16; o > 0; o >>= 1) v += __shfl_xor_sync(0xffffffffu, v, o);
    return v;
}

// -log(sigmoid(x)) = softplus(-x); fast + stable (tol is 1e-3)
__device__ __forceinline__ float nlsig(float x) {
    float z = -x;
    return fmaxf(z, 0.f) + __logf(1.f + __expf(-fabsf(z)));
}

// w2[d] = sum_e att_w_W[d,e] * att_v_W[64+e]
__global__ void precompute_w2(const float* __restrict__ W, const float* __restrict__ vW) {
    const int d = threadIdx.x;
    const float4* Wr = (const float4*)(W + d * 64);
    const float4* vr = (const float4*)(vW + 64);
    float s = 0.f;
#pragma unroll
    for (int e = 0; e < 16; e++) {
        float4 w = __ldg(Wr + e);
        float4 v = __ldg(vr + e);
        s += w.x * v.x + w.y * v.y + w.z * v.z + w.w * v.w;
    }
    g_w2[d] = s;
}

struct Ids { int aid, pid, nid, uid, nrid, prid, nrel; };

__device__ __forceinline__ Ids load_ids(
    const int* __restrict__ u_id, const int* __restrict__ anchor_i_id,
    const int* __restrict__ pos_r_id, const int* __restrict__ pos_i_id,
    const int* __restrict__ neg_r_id, const int* __restrict__ neg_i_id,
    const int* __restrict__ neg_ri_id, int b)
{
    Ids s;
    s.aid  = __ldg(anchor_i_id + b);
    s.pid  = __ldg(pos_i_id + b);
    s.nid  = __ldg(neg_i_id + b);
    s.uid  = __ldg(u_id + b);
    s.nrid = __ldg(neg_ri_id + b);
    s.prid = __ldg(pos_r_id + b);
    s.nrel = __ldg(neg_r_id + b);
    return s;
}

__global__ void __launch_bounds__(THREADS) actr_main(
    const int* __restrict__ u_id, const int* __restrict__ anchor_i_id,
    const int* __restrict__ pos_r_id, const int* __restrict__ pos_i_id,
    const int* __restrict__ neg_r_id, const int* __restrict__ neg_i_id,
    const int* __restrict__ neg_ri_id, const int* __restrict__ item_meta,
    const float* __restrict__ user_emb, const float* __restrict__ rel_emb,
    const float* __restrict__ item_emb, const float* __restrict__ item_emb_r,
    const float* __restrict__ item_bias, const float* __restrict__ rel_bias,
    const float* __restrict__ meta_emb,
    float* __restrict__ out, int B, float invB)
{
    const int lane = threadIdx.x & 31;
    const int wid = threadIdx.x >> 5;
    const int totalWarps = gridDim.x * WARPS_PER_BLOCK;

    // ---- loop-invariant, warp-uniform data (hoisted)
    float2 w2 = __ldg((const float2*)g_w2 + lane);
    float2 re[3];
    float relb[3];
#pragma unroll
    for (int r = 0; r < 3; r++) {
        re[r] = __ldg((const float2*)rel_emb + r * 32 + lane);
        relb[r] = __ldg(rel_bias + r);
    }

    float accSeq = 0.f, accRel = 0.f, accItm = 0.f;

    int b = blockIdx.x * WARPS_PER_BLOCK + wid;

    // ---- pipeline prologue: ids + meta indices for first sample
    Ids cur;
    int4 cma, cmp, cmn;
    if (b < B) {
        cur = load_ids(u_id, anchor_i_id, pos_r_id, pos_i_id, neg_r_id, neg_i_id, neg_ri_id, b);
        cma = __ldg((const int4*)item_meta + cur.aid);
        cmp = __ldg((const int4*)item_meta + cur.pid);
        cmn = __ldg((const int4*)item_meta + cur.nid);
    }

    while (b < B) {
        const int nb = b + totalWarps;

        // ---- issue ALL embedding gathers for current sample (no dependence left)
        float2 u   = __ldg((const float2*)user_emb   + (size_t)cur.uid  * 32 + lane);
        float2 ar  = __ldg((const float2*)item_emb_r + (size_t)cur.aid  * 32 + lane);
        float2 a   = __ldg((const float2*)item_emb   + (size_t)cur.aid  * 32 + lane);
        float2 p   = __ldg((const float2*)item_emb   + (size_t)cur.pid  * 32 + lane);
        float2 n   = __ldg((const float2*)item_emb   + (size_t)cur.nid  * 32 + lane);
        float2 nri = __ldg((const float2*)item_emb   + (size_t)cur.nrid * 32 + lane);

        int cmai[4] = {cma.x, cma.y, cma.z, cma.w};
        int cmpi[4] = {cmp.x, cmp.y, cmp.z, cmp.w};
        int cmni[4] = {cmn.x, cmn.y, cmn.z, cmn.w};
        float2 am[4], pm[4], nm[4];
#pragma unroll
        for (int g = 0; g < 4; g++) {
            am[g] = __ldg((const float2*)meta_emb + (size_t)cmai[g] * 32 + lane);
            pm[g] = __ldg((const float2*)meta_emb + (size_t)cmpi[g] * 32 + lane);
            nm[g] = __ldg((const float2*)meta_emb + (size_t)cmni[g] * 32 + lane);
        }
        float biasP  = __ldg(item_bias + cur.pid);
        float biasN  = __ldg(item_bias + cur.nid);
        float biasNR = __ldg(item_bias + cur.nrid);

        // ---- prefetch NEXT sample's ids (arrive during compute below)
        Ids nxt;
        if (nb < B)
            nxt = load_ids(u_id, anchor_i_id, pos_r_id, pos_i_id, neg_r_id, neg_i_id, neg_ri_id, nb);

        // ---- relation prediction: softmax_r( rel_bias[r] - ||u + a_r - rel_emb[r]||^2 )
        float rw[3];
#pragma unroll
        for (int r = 0; r < 3; r++) {
            float dx = u.x + ar.x - re[r].x;
            float dy = u.y + ar.y - re[r].y;
            rw[r] = relb[r] - wsum(dx * dx + dy * dy);
        }
        float mx = fmaxf(rw[0], fmaxf(rw[1], rw[2]));
        float ssum = 0.f;
#pragma unroll
        for (int r = 0; r < 3; r++) { rw[r] = __expf(rw[r] - mx); ssum += rw[r]; }
        float inv = __frcp_rn(ssum);
#pragma unroll
        for (int r = 0; r < 3; r++) rw[r] *= inv;

        // ---- attention coef: softmax_c( i_plus[c] . w2 )
        float cf[5];
        cf[0] = wsum(a.x * w2.x + a.y * w2.y);
#pragma unroll
        for (int g = 0; g < 4; g++)
            cf[1 + g] = wsum(am[g].x * w2.x + am[g].y * w2.y);
        mx = cf[0];
#pragma unroll
        for (int c = 1; c < 5; c++) mx = fmaxf(mx, cf[c]);
        ssum = 0.f;
#pragma unroll
        for (int c = 0; c < 5; c++) { cf[c] = __expf(cf[c] - mx); ssum += cf[c]; }
        inv = __frcp_rn(ssum);
#pragma unroll
        for (int c = 0; c < 5; c++) cf[c] *= inv;

        // ---- prefetch NEXT sample's meta indices (nxt ids have arrived by now)
        int4 nma, nmp, nmn;
        if (nb < B) {
            nma = __ldg((const int4*)item_meta + nxt.aid);
            nmp = __ldg((const int4*)item_meta + nxt.pid);
            nmn = __ldg((const int4*)item_meta + nxt.nid);
        }

        // ---- rbar = sum_r rel[r]*rue[r]  (||rue||^2 term cancels in pos-neg diff)
        const float GAMMA = 0.5f;
        float2 rbar;
        rbar.x = GAMMA * (rw[0] * re[0].x + rw[1] * re[1].x + rw[2] * re[2].x) + (1.f - GAMMA) * u.x;
        rbar.y = GAMMA * (rw[0] * re[0].y + rw[1] * re[1].y + rw[2] * re[2].y) + (1.f - GAMMA) * u.y;

        // ---- seq score difference in one reduction
        float diffpn;
        {
            float sdp = 0.f, dbxp = 0.f, dbyp = 0.f;
            float sdn = 0.f, dbxn = 0.f, dbyn = 0.f;
            float dx = a.x - p.x, dy = a.y - p.y;
            sdp += cf[0] * (dx * dx + dy * dy); dbxp += cf[0] * dx; dbyp += cf[0] * dy;
            dx = a.x - n.x; dy = a.y - n.y;
            sdn += cf[0] * (dx * dx + dy * dy); dbxn += cf[0] * dx; dbyn += cf[0] * dy;
#pragma unroll
            for (int g = 0; g < 4; g++) {
                dx = am[g].x - pm[g].x; dy = am[g].y - pm[g].y;
                sdp += cf[1 + g] * (dx * dx + dy * dy);
                dbxp += cf[1 + g] * dx; dbyp += cf[1 + g] * dy;
                dx = am[g].x - nm[g].x; dy = am[g].y - nm[g].y;
                sdn += cf[1 + g] * (dx * dx + dy * dy);
                dbxn += cf[1 + g] * dx; dbyn += cf[1 + g] * dy;
            }
            float sp = sdp + 2.f * (dbxp * rbar.x + dbyp * rbar.y);
            float sn = sdn + 2.f * (dbxn * rbar.x + dbyn * rbar.y);
            diffpn = wsum(sp - sn);
        }
        accSeq += nlsig((biasP - biasN) - diffpn);

        // ---- relation loss
        float prs = (cur.prid == 0) ? rw[0] : ((cur.prid == 1) ? rw[1] : rw[2]);
        float nrs = (cur.nrel == 0) ? rw[0] : ((cur.nrel == 1) ? rw[1] : rw[2]);
        accRel += nlsig(prs - nrs);

        // ---- item loss in one reduction
        float2 iir;
        iir.x = (cur.prid == 0) ? re[0].x : ((cur.prid == 1) ? re[1].x : re[2].x);
        iir.y = (cur.prid == 0) ? re[0].y : ((cur.prid == 1) ? re[1].y : re[2].y);
        float px = a.x + iir.x - p.x,   py = a.y + iir.y - p.y;
        float qx = a.x + iir.x - nri.x, qy = a.y + iir.y - nri.y;
        float di = wsum((px * px + py * py) - (qx * qx + qy * qy));
        accItm += nlsig((biasP - biasNR) - di);

        // ---- rotate pipeline
        cur = nxt; cma = nma; cmp = nmp; cmn = nmn;
        b = nb;
    }

    // ---- deterministic block-level partial sum
    __shared__ float sh[WARPS_PER_BLOCK][3];
    __shared__ bool is_last;
    if (lane == 0) { sh[wid][0] = accSeq; sh[wid][1] = accRel; sh[wid][2] = accItm; }
    __syncthreads();
    if (threadIdx.x == 0) {
        float s0 = 0.f, s1 = 0.f, s2 = 0.f;
#pragma unroll
        for (int w = 0; w < WARPS_PER_BLOCK; w++) {
            s0 += sh[w][0]; s1 += sh[w][1]; s2 += sh[w][2];
        }
        g_partials[blockIdx.x * 3 + 0] = s0;
        g_partials[blockIdx.x * 3 + 1] = s1;
        g_partials[blockIdx.x * 3 + 2] = s2;
        __threadfence();
        unsigned int old = atomicAdd(&g_count, 1u);
        is_last = (old == gridDim.x - 1);
    }
    __syncthreads();

    // ---- last arriving block does the final (fixed-order, deterministic) reduce
    if (is_last) {
        const int nblocks = gridDim.x;
        __shared__ float shf[3];
        if (wid < 3) {
            float s = 0.f;
            for (int i = lane; i < nblocks; i += 32) s += g_partials[i * 3 + wid];
            s = wsum(s) * invB;
            if (lane == 0) shf[wid] = s;
        }
        __syncthreads();
        if (threadIdx.x == 0) {
            float seq = shf[0], rel = shf[1], itm = shf[2];
            out[0] = seq + rel + itm;   // loss (ALPHA=BETA=1)
            out[1] = rel;               // relation_loss
            out[2] = seq;               // seq_loss
            out[3] = itm;               // item_loss
            g_count = 0;                // reset for next graph replay
        }
    }
}

extern "C" void kernel_launch(void* const* d_in, const int* in_sizes, int n_in,
                              void* d_out, int out_size) {
    const int*   u_id       = (const int*)d_in[0];
    const int*   anchor_i   = (const int*)d_in[1];
    const int*   pos_r      = (const int*)d_in[2];
    const int*   pos_i      = (const int*)d_in[3];
    const int*   neg_r      = (const int*)d_in[4];
    const int*   neg_i      = (const int*)d_in[5];
    const int*   neg_ri     = (const int*)d_in[6];
    const int*   item_meta  = (const int*)d_in[7];
    const float* user_emb   = (const float*)d_in[8];
    const float* rel_emb    = (const float*)d_in[9];
    const float* item_emb   = (const float*)d_in[10];
    const float* item_emb_r = (const float*)d_in[11];
    const float* item_bias  = (const float*)d_in[12];
    const float* rel_bias   = (const float*)d_in[13];
    const float* meta_emb   = (const float*)d_in[14];
    const float* att_w_W    = (const float*)d_in[15];
    const float* att_v_W    = (const float*)d_in[17];

    const int B = in_sizes[0];
    int nblocks = GRID_BLOCKS;  // ~one resident wave on 148 SMs, warps loop over samples

    precompute_w2<<<1, 64>>>(att_w_W, att_v_W);
    actr_main<<<nblocks, THREADS>>>(u_id, anchor_i, pos_r, pos_i, neg_r, neg_i, neg_ri,
                                    item_meta, user_emb, rel_emb, item_emb, item_emb_r,
                                    item_bias, rel_bias, meta_emb,
                                    (float*)d_out, B, 1.0f / (float)B);
}